// round 13
// baseline (speedup 1.0000x reference)
#include <cuda_runtime.h>
#include <cuda_bf16.h>
#include <cuda_fp16.h>
#include <cstdint>
#include <math.h>

#define NN 50000
#define NE 500000
#define DD 128
#define TM 128

// padded fp16 tile: 128 rows x 136 halves stride (272B = 17*16B -> conflict-free LDSM)
#define TSTRIDE 272
#define TILE_BYTES (128 * TSTRIDE)      // 34816
#define O_BH 0
#define O_ST TILE_BYTES                 // stats (edge kernel): 1KB
#define DSMEM_BYTES (O_ST + 1024)       // 35840
#define SCAN_B 49                       // ceil(50000/1024)

// ---------------- scratch (device globals: no allocations allowed) ----------
__device__ float g_Ah[NN * DD];
__device__ float g_Bh[NN * DD];
__device__ float g_Dh[NN * DD];
__device__ float g_Eh[NN * DD];
__device__ float g_hnew[NN * DD];
__device__ float g_enew[(size_t)NE * DD];
__device__ float g_stats[4 * DD];   // [sum_e | sumsq_e | sum_h | sumsq_h]
__device__ int   g_cnt[NN];
__device__ int   g_cur[NN];
__device__ int   g_off[NN + 1];
__device__ int   g_eid[NE];
__device__ int   g_bsum[64];
__device__ int   g_bpre[64];
// pre-converted weights (fp16, packed row-major): w: 0=A,1=B,2=D,3=E,4=C
__device__ __align__(16) unsigned short g_Wh[5 * DD * DD];

// ================= warp-MMA helpers (baseline ISA: ldmatrix + mma.sync) =====
__device__ __forceinline__ uint32_t smem_u32(const void* p) {
    uint32_t a;
    asm("{ .reg .u64 t; cvta.to.shared.u64 t, %1; cvt.u32.u64 %0, t; }" : "=r"(a) : "l"(p));
    return a;
}

#define LDSM4(r, addr) \
    asm volatile("ldmatrix.sync.aligned.m8n8.x4.shared.b16 {%0,%1,%2,%3}, [%4];" \
        : "=r"((r)[0]), "=r"((r)[1]), "=r"((r)[2]), "=r"((r)[3]) : "r"(addr))

__device__ __forceinline__ void mma_f16(float* c, const uint32_t* a, const uint32_t* b) {
    asm volatile(
        "mma.sync.aligned.m16n8k16.row.col.f32.f16.f16.f32 "
        "{%0,%1,%2,%3}, {%4,%5,%6,%7}, {%8,%9}, {%0,%1,%2,%3};"
        : "+f"(c[0]), "+f"(c[1]), "+f"(c[2]), "+f"(c[3])
        : "r"(a[0]), "r"(a[1]), "r"(a[2]), "r"(a[3]), "r"(b[0]), "r"(b[1]));
}

// fp32x2 -> packed fp16 hi reg + fp16 lo (residual) reg; low half = first elem
#define CONVHL16(v, hreg, lreg) do { \
    asm("cvt.rn.f16x2.f32 %0, %1, %2;" : "=r"(hreg) : "f"((v).y), "f"((v).x)); \
    __half2 _hh = *(__half2*)&(hreg); \
    float _h0 = __half2float(__low2half(_hh)); \
    float _h1 = __half2float(__high2half(_hh)); \
    float _l0 = (v).x - _h0, _l1 = (v).y - _h1; \
    asm("cvt.rn.f16x2.f32 %0, %1, %2;" : "=r"(lreg) : "f"(_l1), "f"(_l0)); \
} while (0)

// copy a pre-converted 128x128 fp16 weight (packed 256B rows) into padded smem
__device__ __forceinline__ void copy_w(const unsigned short* __restrict__ g,
                                       char* s, int tid)
{
#pragma unroll
    for (int i = 0; i < 8; i++) {
        int idx = tid + i * 256;          // 2048 16B chunks
        int r = idx >> 4;
        int cb = (idx & 15) << 4;
        uint4 v = *(const uint4*)((const char*)g + r * 256 + cb);
        *(uint4*)(s + r * TSTRIDE + cb) = v;
    }
}

// 128x(64)x128 fp16x2 warp-MMA: warp (wm,wn) owns rows wm*32..+31, cols wn*64..+63.
// A hi/lo corrected from global; B single fp16 from smem.
// acc[(mt*4+p)*8 + sub*4 + hf*2 + e]: mt=m16 tile, p=16-col group, sub=n8 half, hf=row half.
__device__ __forceinline__ void mma_regA2(
    const float* __restrict__ src, int row0, int M,
    uint32_t sB, int wm, int wn, int lane, float* acc)
{
    const int q = lane >> 2;
    const int kb = (lane & 3) * 2;
    const int r0 = row0 + wm * 32 + q;
    const float* p00 = src + (size_t)r0 * DD + kb;
    const float* p01 = p00 + 8 * DD;
    const float* p10 = p00 + 16 * DD;
    const float* p11 = p00 + 24 * DD;
    const bool g00 = r0 < M, g01 = r0 + 8 < M, g10 = r0 + 16 < M, g11 = r0 + 24 < M;
    const uint32_t boff = sB + (uint32_t)((((lane & 7) + ((lane >> 4) & 1) * 8) + wn * 64) * TSTRIDE
                                          + (((lane >> 3) & 1) * 16));
    const float2 z = make_float2(0.f, 0.f);

#pragma unroll
    for (int ks = 0; ks < 8; ks++) {
        float2 a00 = g00 ? *(const float2*)(p00 + ks * 16)     : z;
        float2 a01 = g01 ? *(const float2*)(p01 + ks * 16)     : z;
        float2 a02 = g00 ? *(const float2*)(p00 + ks * 16 + 8) : z;
        float2 a03 = g01 ? *(const float2*)(p01 + ks * 16 + 8) : z;
        float2 a10 = g10 ? *(const float2*)(p10 + ks * 16)     : z;
        float2 a11 = g11 ? *(const float2*)(p11 + ks * 16)     : z;
        float2 a12 = g10 ? *(const float2*)(p10 + ks * 16 + 8) : z;
        float2 a13 = g11 ? *(const float2*)(p11 + ks * 16 + 8) : z;
        uint32_t ah0[4], al0[4], ah1[4], al1[4];
        CONVHL16(a00, ah0[0], al0[0]);
        CONVHL16(a01, ah0[1], al0[1]);
        CONVHL16(a02, ah0[2], al0[2]);
        CONVHL16(a03, ah0[3], al0[3]);
        CONVHL16(a10, ah1[0], al1[0]);
        CONVHL16(a11, ah1[1], al1[1]);
        CONVHL16(a12, ah1[2], al1[2]);
        CONVHL16(a13, ah1[3], al1[3]);
#pragma unroll
        for (int p = 0; p < 4; p++) {
            uint32_t b[4];
            LDSM4(b, boff + (uint32_t)(p * 16 * TSTRIDE + ks * 32));
            float* c00 = acc + (0 * 4 + p) * 8;
            float* c10 = acc + (1 * 4 + p) * 8;
            mma_f16(c00,     ah0, &b[0]);
            mma_f16(c00 + 4, ah0, &b[2]);
            mma_f16(c00,     al0, &b[0]);
            mma_f16(c00 + 4, al0, &b[2]);
            mma_f16(c10,     ah1, &b[0]);
            mma_f16(c10 + 4, ah1, &b[2]);
            mma_f16(c10,     al1, &b[0]);
            mma_f16(c10 + 4, al1, &b[2]);
        }
    }
}

// ---------------- weight pre-conversion (runs once per call, tiny) ----------
__global__ void k_convW(const float* __restrict__ WA, const float* __restrict__ WB,
                        const float* __restrict__ WD, const float* __restrict__ WE,
                        const float* __restrict__ WC)
{
    int w = blockIdx.y;
    int i = blockIdx.x * 256 + threadIdx.x;   // 0..16383
    const float* Ws = (w == 0) ? WA : (w == 1) ? WB : (w == 2) ? WD : (w == 3) ? WE : WC;
    g_Wh[w * DD * DD + i] = __half_as_ushort(__float2half_rn(Ws[i]));
}

// ---------------- zero counters ---------------------------------------------
__global__ void k_zero() {
    int idx = blockIdx.x * blockDim.x + threadIdx.x;
    if (idx < NN) { g_cnt[idx] = 0; g_cur[idx] = 0; }
    if (idx < 4 * DD) g_stats[idx] = 0.f;
}

// ---------------- CSR build: histogram, 3-phase scan, scatter ----------------
__global__ void k_hist(const int* __restrict__ dst) {
    int e = blockIdx.x * blockDim.x + threadIdx.x;
    if (e < NE) atomicAdd(&g_cnt[dst[e]], 1);
}

__global__ void k_scan1() {   // SCAN_B blocks x 1024: block sums
    __shared__ int ws[32];
    const int tid = threadIdx.x, lane = tid & 31, wid = tid >> 5;
    int i = blockIdx.x * 1024 + tid;
    int v = (i < NN) ? g_cnt[i] : 0;
#pragma unroll
    for (int o = 16; o > 0; o >>= 1) v += __shfl_down_sync(~0u, v, o);
    if (lane == 0) ws[wid] = v;
    __syncthreads();
    if (wid == 0) {
        int x = ws[lane];
#pragma unroll
        for (int o = 16; o > 0; o >>= 1) x += __shfl_down_sync(~0u, x, o);
        if (lane == 0) g_bsum[blockIdx.x] = x;
    }
}

__global__ void k_scan2() {   // 1 warp: exclusive scan of SCAN_B block sums
    const int lane = threadIdx.x;
    int i0 = lane * 2, i1 = lane * 2 + 1;
    int a = (i0 < SCAN_B) ? g_bsum[i0] : 0;
    int b = (i1 < SCAN_B) ? g_bsum[i1] : 0;
    int ps = a + b;
    int x = ps;
#pragma unroll
    for (int o = 1; o < 32; o <<= 1) {
        int y = __shfl_up_sync(~0u, x, o);
        if (lane >= o) x += y;
    }
    int excl = x - ps;
    if (i0 < SCAN_B) g_bpre[i0] = excl;
    if (i1 < SCAN_B) g_bpre[i1] = excl + a;
    if (lane == 31) g_off[NN] = x;
}

__global__ void k_scan3() {   // SCAN_B blocks x 1024: local scan + prefix
    __shared__ int warpsum[32];
    const int tid = threadIdx.x, lane = tid & 31, wid = tid >> 5;
    int i = blockIdx.x * 1024 + tid;
    int v = (i < NN) ? g_cnt[i] : 0;
    int x = v;
#pragma unroll
    for (int o = 1; o < 32; o <<= 1) {
        int y = __shfl_up_sync(~0u, x, o);
        if (lane >= o) x += y;
    }
    if (lane == 31) warpsum[wid] = x;
    __syncthreads();
    if (wid == 0) {
        int w = warpsum[lane];
#pragma unroll
        for (int o = 1; o < 32; o <<= 1) {
            int y = __shfl_up_sync(~0u, w, o);
            if (lane >= o) w += y;
        }
        warpsum[lane] = w;
    }
    __syncthreads();
    int incl = x + (wid ? warpsum[wid - 1] : 0);
    if (i < NN) g_off[i] = g_bpre[blockIdx.x] + incl - v;
}

__global__ void k_scatter(const int* __restrict__ dst) {
    int e = blockIdx.x * blockDim.x + threadIdx.x;
    if (e < NE) {
        int d = dst[e];
        int pos = g_off[d] + atomicAdd(&g_cur[d], 1);
        g_eid[pos] = e;
    }
}

// ---------------- fused 4-weight node GEMM -----------------------------------
__global__ __launch_bounds__(256, 2) void k_gemm4(
    const float* __restrict__ A,
    const float* __restrict__ bA, const float* __restrict__ bB,
    const float* __restrict__ bD, const float* __restrict__ bE,
    float* __restrict__ oA, float* __restrict__ oB,
    float* __restrict__ oD, float* __restrict__ oE)
{
    extern __shared__ __align__(16) char sb[];
    const int tid = threadIdx.x, wid = tid >> 5, lane = tid & 31;
    const int wm = wid >> 1, wn = wid & 1;
    const int row0 = blockIdx.x * TM;
    const uint32_t sbase = smem_u32(sb);
    const int q = lane >> 2, cpair = (lane & 3) * 2;

#pragma unroll 1
    for (int w = 0; w < 4; w++) {
        copy_w(g_Wh + w * DD * DD, sb + O_BH, tid);
        __syncthreads();

        float acc[64];
#pragma unroll
        for (int i = 0; i < 64; i++) acc[i] = 0.f;
        mma_regA2(A, row0, NN, sbase + O_BH, wm, wn, lane, acc);

        const float* bias = (w == 0) ? bA : (w == 1) ? bB : (w == 2) ? bD : bE;
        float* out = (w == 0) ? oA : (w == 1) ? oB : (w == 2) ? oD : oE;

#pragma unroll
        for (int mt = 0; mt < 2; mt++)
#pragma unroll
        for (int hf = 0; hf < 2; hf++) {
            int m = row0 + wm * 32 + mt * 16 + hf * 8 + q;
            if (m < NN) {
                float* op = out + (size_t)m * DD + wn * 64;
#pragma unroll
                for (int p = 0; p < 4; p++)
#pragma unroll
                for (int sub = 0; sub < 2; sub++) {
                    int co = p * 16 + sub * 8 + cpair;
                    float2 bv = *(const float2*)(bias + wn * 64 + co);
                    float2 v;
                    v.x = acc[(mt * 4 + p) * 8 + sub * 4 + hf * 2 + 0] + bv.x;
                    v.y = acc[(mt * 4 + p) * 8 + sub * 4 + hf * 2 + 1] + bv.y;
                    *(float2*)(op + co) = v;
                }
            }
        }
        __syncthreads();   // before overwriting W tile
    }
}

// ---------------- fused edge kernel (fragment-direct epilogue) ---------------
// Ce = e @ W_C^T; e_new = Ce + bC + Dh[src] + Eh[dst]; store e_new; col stats.
__global__ __launch_bounds__(256, 2) void k_edge_tc(
    const float* __restrict__ Ein,
    const float* __restrict__ bias,
    const int* __restrict__ src, const int* __restrict__ dst)
{
    extern __shared__ __align__(16) char sb[];
    float* shs = (float*)(sb + O_ST);
    float* shq = shs + DD;
    const int tid = threadIdx.x, wid = tid >> 5, lane = tid & 31;
    const int wm = wid >> 1, wn = wid & 1;
    const int row0 = blockIdx.x * TM;
    const int q = lane >> 2, cpair = (lane & 3) * 2;

    if (tid < DD) { shs[tid] = 0.f; shq[tid] = 0.f; }

    copy_w(g_Wh + 4 * DD * DD, sb + O_BH, tid);

    // prefetch gather indices (overlap with weight copy + MMA)
    int sA[4], dA[4];
#pragma unroll
    for (int i = 0; i < 4; i++) {
        int m = row0 + wm * 32 + (i >> 1) * 16 + (i & 1) * 8 + q;
        sA[i] = (m < NE) ? src[m] : 0;
        dA[i] = (m < NE) ? dst[m] : 0;
    }
    __syncthreads();

    float acc[64];
#pragma unroll
    for (int i = 0; i < 64; i++) acc[i] = 0.f;
    mma_regA2(Ein, row0, NE, smem_u32(sb) + O_BH, wm, wn, lane, acc);

    // fragment-direct epilogue: no staging, no barriers
    float cs[16], cq[16];
#pragma unroll
    for (int i = 0; i < 16; i++) { cs[i] = 0.f; cq[i] = 0.f; }

#pragma unroll
    for (int mt = 0; mt < 2; mt++)
#pragma unroll
    for (int hf = 0; hf < 2; hf++) {
        int m = row0 + wm * 32 + mt * 16 + hf * 8 + q;
        if (m < NE) {
            const float* Dr = g_Dh + (size_t)sA[mt * 2 + hf] * DD + wn * 64;
            const float* Er = g_Eh + (size_t)dA[mt * 2 + hf] * DD + wn * 64;
            float* ep = g_enew + (size_t)m * DD + wn * 64;
#pragma unroll
            for (int p = 0; p < 4; p++)
#pragma unroll
            for (int sub = 0; sub < 2; sub++) {
                int co = p * 16 + sub * 8 + cpair;
                float2 Dv = *(const float2*)(Dr + co);
                float2 Ev = *(const float2*)(Er + co);
                float2 bv = *(const float2*)(bias + wn * 64 + co);
                float e0 = acc[(mt * 4 + p) * 8 + sub * 4 + hf * 2 + 0] + bv.x + Dv.x + Ev.x;
                float e1 = acc[(mt * 4 + p) * 8 + sub * 4 + hf * 2 + 1] + bv.y + Dv.y + Ev.y;
                float2 o = {e0, e1};
                *(float2*)(ep + co) = o;
                int si = (p * 2 + sub) * 2;
                cs[si]     += e0;  cs[si + 1] += e1;
                cq[si]     += e0 * e0;  cq[si + 1] += e1 * e1;
            }
        }
    }

    // reduce stats across the 8 quads (rows) of the warp
#pragma unroll
    for (int i = 0; i < 16; i++) {
#pragma unroll
        for (int o = 4; o < 32; o <<= 1) {
            cs[i] += __shfl_xor_sync(~0u, cs[i], o);
            cq[i] += __shfl_xor_sync(~0u, cq[i], o);
        }
    }
    if (lane < 4) {
#pragma unroll
        for (int p = 0; p < 4; p++)
#pragma unroll
        for (int sub = 0; sub < 2; sub++)
#pragma unroll
        for (int e2 = 0; e2 < 2; e2++) {
            int col = wn * 64 + p * 16 + sub * 8 + lane * 2 + e2;
            int si = (p * 2 + sub) * 2 + e2;
            atomicAdd(&shs[col], cs[si]);
            atomicAdd(&shq[col], cq[si]);
        }
    }
    __syncthreads();
    if (tid < DD) {
        atomicAdd(&g_stats[tid], shs[tid]);
        atomicAdd(&g_stats[DD + tid], shq[tid]);
    }
}

// ---------------- gather-side aggregation + h_new + h stats ------------------
__global__ __launch_bounds__(128) void k_agg(const int* __restrict__ src) {
    const int col = threadIdx.x;   // 0..127
    float ls = 0.f, lq = 0.f;
    for (int n = blockIdx.x; n < NN; n += gridDim.x) {
        int s0 = g_off[n], s1 = g_off[n + 1];
        float num = 0.f, den = 0.f;
        int eid_n = 0, sv_n = 0;
        if (s0 < s1) { eid_n = g_eid[s0]; sv_n = src[eid_n]; }
        for (int i = s0; i < s1; i++) {
            int eid = eid_n, sv = sv_n;
            if (i + 1 < s1) { eid_n = g_eid[i + 1]; sv_n = src[eid_n]; }
            float en = g_enew[(size_t)eid * DD + col];
            float bh = g_Bh[(size_t)sv * DD + col];
            float sg = 1.f / (1.f + __expf(-en));
            den += sg;
            num += bh * sg;
        }
        float v = g_Ah[(size_t)n * DD + col] + num / (den + 1e-6f);
        g_hnew[(size_t)n * DD + col] = v;
        ls += v; lq += v * v;
    }
    atomicAdd(&g_stats[2 * DD + col], ls);
    atomicAdd(&g_stats[3 * DD + col], lq);
}

// ---------------- BN(train) + relu + residual epilogue ----------------------
__global__ void k_out(const float* __restrict__ x, const float* __restrict__ v,
                      const float* __restrict__ gamma, const float* __restrict__ beta,
                      float* __restrict__ out, size_t n4, int statbase, float invM)
{
    __shared__ float sc[DD];
    __shared__ float sf[DD];
    const int tid = threadIdx.x;
    if (tid < DD) {
        float mean = g_stats[statbase * DD + tid] * invM;
        float var = g_stats[(statbase + 1) * DD + tid] * invM - mean * mean;
        float s = rsqrtf(var + 1e-5f) * gamma[tid];
        sc[tid] = s;
        sf[tid] = beta[tid] - mean * s;
    }
    __syncthreads();
    size_t i = (size_t)blockIdx.x * 256 + tid;
    if (i < n4) {
        int c0 = (int)((i * 4) & (DD - 1));
        float4 vv = ((const float4*)v)[i];
        float4 xx = ((const float4*)x)[i];
        float4 o;
        o.x = xx.x + fmaxf(fmaf(vv.x, sc[c0 + 0], sf[c0 + 0]), 0.f);
        o.y = xx.y + fmaxf(fmaf(vv.y, sc[c0 + 1], sf[c0 + 1]), 0.f);
        o.z = xx.z + fmaxf(fmaf(vv.z, sc[c0 + 2], sf[c0 + 2]), 0.f);
        o.w = xx.w + fmaxf(fmaf(vv.w, sc[c0 + 3], sf[c0 + 3]), 0.f);
        ((float4*)out)[i] = o;
    }
}

// ---------------- host orchestration ----------------------------------------
extern "C" void kernel_launch(void* const* d_in, const int* in_sizes, int n_in,
                              void* d_out, int out_size)
{
    const float* h   = (const float*)d_in[0];
    const float* e   = (const float*)d_in[1];
    const int* src   = (const int*)d_in[2];
    const int* dst   = (const int*)d_in[3];
    const float* W_A = (const float*)d_in[4];
    const float* b_A = (const float*)d_in[5];
    const float* W_B = (const float*)d_in[6];
    const float* b_B = (const float*)d_in[7];
    const float* W_C = (const float*)d_in[8];
    const float* b_C = (const float*)d_in[9];
    const float* W_D = (const float*)d_in[10];
    const float* b_D = (const float*)d_in[11];
    const float* W_E = (const float*)d_in[12];
    const float* b_E = (const float*)d_in[13];
    const float* gamma_h = (const float*)d_in[14];
    const float* beta_h  = (const float*)d_in[15];
    const float* gamma_e = (const float*)d_in[16];
    const float* beta_e  = (const float*)d_in[17];
    float* out = (float*)d_out;

    float *pAh, *pBh, *pDh, *pEh, *pHnew, *pEnew;
    cudaGetSymbolAddress((void**)&pAh, g_Ah);
    cudaGetSymbolAddress((void**)&pBh, g_Bh);
    cudaGetSymbolAddress((void**)&pDh, g_Dh);
    cudaGetSymbolAddress((void**)&pEh, g_Eh);
    cudaGetSymbolAddress((void**)&pHnew, g_hnew);
    cudaGetSymbolAddress((void**)&pEnew, g_enew);

    cudaFuncSetAttribute(k_gemm4, cudaFuncAttributeMaxDynamicSharedMemorySize, DSMEM_BYTES);
    cudaFuncSetAttribute(k_edge_tc, cudaFuncAttributeMaxDynamicSharedMemorySize, DSMEM_BYTES);

    const int gemmN = (NN + TM - 1) / TM;   // 391
    const int gemmE = (NE + TM - 1) / TM;   // 3907

    // submission order puts k_edge_tc 4th (ncu capture lands on launch #4)
    k_zero<<<(NN + 255) / 256, 256>>>();
    {
        dim3 g(DD * DD / 256, 5);
        k_convW<<<g, 256>>>(W_A, W_B, W_D, W_E, W_C);
    }
    k_gemm4<<<gemmN, 256, DSMEM_BYTES>>>(h, b_A, b_B, b_D, b_E, pAh, pBh, pDh, pEh);
    k_edge_tc<<<gemmE, 256, DSMEM_BYTES>>>(e, b_C, src, dst);
    k_hist<<<(NE + 255) / 256, 256>>>(dst);
    k_scan1<<<SCAN_B, 1024>>>();
    k_scan2<<<1, 32>>>();
    k_scan3<<<SCAN_B, 1024>>>();
    k_scatter<<<(NE + 255) / 256, 256>>>(dst);
    k_agg<<<4096, 128>>>(src);
    // e_out: rows after h_out section
    k_out<<<(int)(((size_t)NE * DD / 4 + 255) / 256), 256>>>(
        e, pEnew, gamma_e, beta_e, out + (size_t)NN * DD, (size_t)NE * DD / 4, 0, 1.f / NE);
    // h_out at the front of d_out
    k_out<<<(int)(((size_t)NN * DD / 4 + 255) / 256), 256>>>(
        h, pHnew, gamma_h, beta_h, out, (size_t)NN * DD / 4, 2, 1.f / NN);
}

// round 15
// speedup vs baseline: 1.0437x; 1.0437x over previous
#include <cuda_runtime.h>
#include <cuda_bf16.h>
#include <cuda_fp16.h>
#include <cstdint>
#include <math.h>

#define NN 50000
#define NE 500000
#define DD 128
#define TM 128

// padded fp16 tile: 128 rows x 136 halves stride (272B = 17*16B -> conflict-free LDSM)
#define TSTRIDE 272
#define TILE_BYTES (128 * TSTRIDE)      // 34816
#define O_BH 0
// C staging (floats, stride 132) overlays from 0: 128*132*4 = 67584
#define CSTRIDE 132
#define O_ST 67584                      // stats: 1KB
#define DSMEM_BYTES (O_ST + 1024)       // 68608 -> 2 CTAs/SM (reg-limited anyway)
#define SCAN_B 49                       // ceil(50000/1024)

// ---------------- scratch (device globals: no allocations allowed) ----------
__device__ float g_Ah[NN * DD];
__device__ float g_Bh[NN * DD];
__device__ float g_Dh[NN * DD];
__device__ float g_Eh[NN * DD];
__device__ float g_hnew[NN * DD];
__device__ float g_enew[(size_t)NE * DD];
__device__ float g_stats[4 * DD];   // [sum_e | sumsq_e | sum_h | sumsq_h]
__device__ int   g_cnt[NN];
__device__ int   g_cur[NN];
__device__ int   g_off[NN + 1];
__device__ int   g_eid[NE];
__device__ int   g_bsum[64];
__device__ int   g_bpre[64];
// pre-converted weights (fp16, packed row-major): w: 0=A,1=B,2=D,3=E,4=C
__device__ __align__(16) unsigned short g_Wh[5 * DD * DD];

// ================= warp-MMA helpers (baseline ISA: ldmatrix + mma.sync) =====
__device__ __forceinline__ uint32_t smem_u32(const void* p) {
    uint32_t a;
    asm("{ .reg .u64 t; cvta.to.shared.u64 t, %1; cvt.u32.u64 %0, t; }" : "=r"(a) : "l"(p));
    return a;
}

#define LDSM4(r, addr) \
    asm volatile("ldmatrix.sync.aligned.m8n8.x4.shared.b16 {%0,%1,%2,%3}, [%4];" \
        : "=r"((r)[0]), "=r"((r)[1]), "=r"((r)[2]), "=r"((r)[3]) : "r"(addr))

__device__ __forceinline__ void mma_f16(float* c, const uint32_t* a, const uint32_t* b) {
    asm volatile(
        "mma.sync.aligned.m16n8k16.row.col.f32.f16.f16.f32 "
        "{%0,%1,%2,%3}, {%4,%5,%6,%7}, {%8,%9}, {%0,%1,%2,%3};"
        : "+f"(c[0]), "+f"(c[1]), "+f"(c[2]), "+f"(c[3])
        : "r"(a[0]), "r"(a[1]), "r"(a[2]), "r"(a[3]), "r"(b[0]), "r"(b[1]));
}

// fp32x2 -> packed fp16 hi reg + fp16 lo (residual) reg; low half = first elem
#define CONVHL16(v, hreg, lreg) do { \
    asm("cvt.rn.f16x2.f32 %0, %1, %2;" : "=r"(hreg) : "f"((v).y), "f"((v).x)); \
    __half2 _hh = *(__half2*)&(hreg); \
    float _h0 = __half2float(__low2half(_hh)); \
    float _h1 = __half2float(__high2half(_hh)); \
    float _l0 = (v).x - _h0, _l1 = (v).y - _h1; \
    asm("cvt.rn.f16x2.f32 %0, %1, %2;" : "=r"(lreg) : "f"(_l1), "f"(_l0)); \
} while (0)

// copy a pre-converted 128x128 fp16 weight (packed 256B rows) into padded smem
__device__ __forceinline__ void copy_w(const unsigned short* __restrict__ g,
                                       char* s, int tid)
{
#pragma unroll
    for (int i = 0; i < 8; i++) {
        int idx = tid + i * 256;          // 2048 16B chunks
        int r = idx >> 4;
        int cb = (idx & 15) << 4;
        uint4 v = *(const uint4*)((const char*)g + r * 256 + cb);
        *(uint4*)(s + r * TSTRIDE + cb) = v;
    }
}

// 128x(64)x128 fp16x2 warp-MMA: warp (wm,wn) owns rows wm*32..+31, cols wn*64..+63.
// A hi/lo corrected from global; B single fp16 from smem.
// acc[(mt*4+p)*8 + sub*4 + hf*2 + e]: mt=m16 tile, p=16-col group, sub=n8 half, hf=row half.
__device__ __forceinline__ void mma_regA2(
    const float* __restrict__ src, int row0, int M,
    uint32_t sB, int wm, int wn, int lane, float* acc)
{
    const int q = lane >> 2;
    const int kb = (lane & 3) * 2;
    const int r0 = row0 + wm * 32 + q;
    const float* p00 = src + (size_t)r0 * DD + kb;
    const float* p01 = p00 + 8 * DD;
    const float* p10 = p00 + 16 * DD;
    const float* p11 = p00 + 24 * DD;
    const bool g00 = r0 < M, g01 = r0 + 8 < M, g10 = r0 + 16 < M, g11 = r0 + 24 < M;
    const uint32_t boff = sB + (uint32_t)((((lane & 7) + ((lane >> 4) & 1) * 8) + wn * 64) * TSTRIDE
                                          + (((lane >> 3) & 1) * 16));
    const float2 z = make_float2(0.f, 0.f);

#pragma unroll
    for (int ks = 0; ks < 8; ks++) {
        float2 a00 = g00 ? *(const float2*)(p00 + ks * 16)     : z;
        float2 a01 = g01 ? *(const float2*)(p01 + ks * 16)     : z;
        float2 a02 = g00 ? *(const float2*)(p00 + ks * 16 + 8) : z;
        float2 a03 = g01 ? *(const float2*)(p01 + ks * 16 + 8) : z;
        float2 a10 = g10 ? *(const float2*)(p10 + ks * 16)     : z;
        float2 a11 = g11 ? *(const float2*)(p11 + ks * 16)     : z;
        float2 a12 = g10 ? *(const float2*)(p10 + ks * 16 + 8) : z;
        float2 a13 = g11 ? *(const float2*)(p11 + ks * 16 + 8) : z;
        uint32_t ah0[4], al0[4], ah1[4], al1[4];
        CONVHL16(a00, ah0[0], al0[0]);
        CONVHL16(a01, ah0[1], al0[1]);
        CONVHL16(a02, ah0[2], al0[2]);
        CONVHL16(a03, ah0[3], al0[3]);
        CONVHL16(a10, ah1[0], al1[0]);
        CONVHL16(a11, ah1[1], al1[1]);
        CONVHL16(a12, ah1[2], al1[2]);
        CONVHL16(a13, ah1[3], al1[3]);
#pragma unroll
        for (int p = 0; p < 4; p++) {
            uint32_t b[4];
            LDSM4(b, boff + (uint32_t)(p * 16 * TSTRIDE + ks * 32));
            float* c00 = acc + (0 * 4 + p) * 8;
            float* c10 = acc + (1 * 4 + p) * 8;
            mma_f16(c00,     ah0, &b[0]);
            mma_f16(c00 + 4, ah0, &b[2]);
            mma_f16(c00,     al0, &b[0]);
            mma_f16(c00 + 4, al0, &b[2]);
            mma_f16(c10,     ah1, &b[0]);
            mma_f16(c10 + 4, ah1, &b[2]);
            mma_f16(c10,     al1, &b[0]);
            mma_f16(c10 + 4, al1, &b[2]);
        }
    }
}

// ---------------- weight pre-conversion (runs once per call, tiny) ----------
__global__ void k_convW(const float* __restrict__ WA, const float* __restrict__ WB,
                        const float* __restrict__ WD, const float* __restrict__ WE,
                        const float* __restrict__ WC)
{
    int w = blockIdx.y;
    int i = blockIdx.x * 256 + threadIdx.x;   // 0..16383
    const float* Ws = (w == 0) ? WA : (w == 1) ? WB : (w == 2) ? WD : (w == 3) ? WE : WC;
    g_Wh[w * DD * DD + i] = __half_as_ushort(__float2half_rn(Ws[i]));
}

// ---------------- zero counters ---------------------------------------------
__global__ void k_zero() {
    int idx = blockIdx.x * blockDim.x + threadIdx.x;
    if (idx < NN) { g_cnt[idx] = 0; g_cur[idx] = 0; }
    if (idx < 4 * DD) g_stats[idx] = 0.f;
}

// ---------------- CSR build: histogram, 3-phase scan, scatter ----------------
__global__ void k_hist(const int* __restrict__ dst) {
    int e = blockIdx.x * blockDim.x + threadIdx.x;
    if (e < NE) atomicAdd(&g_cnt[dst[e]], 1);
}

__global__ void k_scan1() {   // SCAN_B blocks x 1024: block sums
    __shared__ int ws[32];
    const int tid = threadIdx.x, lane = tid & 31, wid = tid >> 5;
    int i = blockIdx.x * 1024 + tid;
    int v = (i < NN) ? g_cnt[i] : 0;
#pragma unroll
    for (int o = 16; o > 0; o >>= 1) v += __shfl_down_sync(~0u, v, o);
    if (lane == 0) ws[wid] = v;
    __syncthreads();
    if (wid == 0) {
        int x = ws[lane];
#pragma unroll
        for (int o = 16; o > 0; o >>= 1) x += __shfl_down_sync(~0u, x, o);
        if (lane == 0) g_bsum[blockIdx.x] = x;
    }
}

__global__ void k_scan2() {   // 1 warp: exclusive scan of SCAN_B block sums
    const int lane = threadIdx.x;
    int i0 = lane * 2, i1 = lane * 2 + 1;
    int a = (i0 < SCAN_B) ? g_bsum[i0] : 0;
    int b = (i1 < SCAN_B) ? g_bsum[i1] : 0;
    int ps = a + b;
    int x = ps;
#pragma unroll
    for (int o = 1; o < 32; o <<= 1) {
        int y = __shfl_up_sync(~0u, x, o);
        if (lane >= o) x += y;
    }
    int excl = x - ps;
    if (i0 < SCAN_B) g_bpre[i0] = excl;
    if (i1 < SCAN_B) g_bpre[i1] = excl + a;
    if (lane == 31) g_off[NN] = x;
}

__global__ void k_scan3() {   // SCAN_B blocks x 1024: local scan + prefix
    __shared__ int warpsum[32];
    const int tid = threadIdx.x, lane = tid & 31, wid = tid >> 5;
    int i = blockIdx.x * 1024 + tid;
    int v = (i < NN) ? g_cnt[i] : 0;
    int x = v;
#pragma unroll
    for (int o = 1; o < 32; o <<= 1) {
        int y = __shfl_up_sync(~0u, x, o);
        if (lane >= o) x += y;
    }
    if (lane == 31) warpsum[wid] = x;
    __syncthreads();
    if (wid == 0) {
        int w = warpsum[lane];
#pragma unroll
        for (int o = 1; o < 32; o <<= 1) {
            int y = __shfl_up_sync(~0u, w, o);
            if (lane >= o) w += y;
        }
        warpsum[lane] = w;
    }
    __syncthreads();
    int incl = x + (wid ? warpsum[wid - 1] : 0);
    if (i < NN) g_off[i] = g_bpre[blockIdx.x] + incl - v;
}

__global__ void k_scatter(const int* __restrict__ dst) {
    int e = blockIdx.x * blockDim.x + threadIdx.x;
    if (e < NE) {
        int d = dst[e];
        int pos = g_off[d] + atomicAdd(&g_cur[d], 1);
        g_eid[pos] = e;
    }
}

// ---------------- fused 4-weight node GEMM (2-D warp tiling) -----------------
__global__ __launch_bounds__(256, 2) void k_gemm4(
    const float* __restrict__ A,
    const float* __restrict__ bA, const float* __restrict__ bB,
    const float* __restrict__ bD, const float* __restrict__ bE,
    float* __restrict__ oA, float* __restrict__ oB,
    float* __restrict__ oD, float* __restrict__ oE)
{
    extern __shared__ __align__(16) char sb[];
    const int tid = threadIdx.x, wid = tid >> 5, lane = tid & 31;
    const int wm = wid >> 1, wn = wid & 1;
    const int row0 = blockIdx.x * TM;
    const uint32_t sbase = smem_u32(sb);
    const int q = lane >> 2, cpair = (lane & 3) * 2;

#pragma unroll 1
    for (int w = 0; w < 4; w++) {
        copy_w(g_Wh + w * DD * DD, sb + O_BH, tid);
        __syncthreads();

        float acc[64];
#pragma unroll
        for (int i = 0; i < 64; i++) acc[i] = 0.f;
        mma_regA2(A, row0, NN, sbase + O_BH, wm, wn, lane, acc);

        const float* bias = (w == 0) ? bA : (w == 1) ? bB : (w == 2) ? bD : bE;
        float* out = (w == 0) ? oA : (w == 1) ? oB : (w == 2) ? oD : oE;

#pragma unroll
        for (int mt = 0; mt < 2; mt++)
#pragma unroll
        for (int hf = 0; hf < 2; hf++) {
            int m = row0 + wm * 32 + mt * 16 + hf * 8 + q;
            if (m < NN) {
                float* op = out + (size_t)m * DD + wn * 64;
#pragma unroll
                for (int p = 0; p < 4; p++)
#pragma unroll
                for (int sub = 0; sub < 2; sub++) {
                    int co = p * 16 + sub * 8 + cpair;
                    float2 bv = *(const float2*)(bias + wn * 64 + co);
                    float2 v;
                    v.x = acc[(mt * 4 + p) * 8 + sub * 4 + hf * 2 + 0] + bv.x;
                    v.y = acc[(mt * 4 + p) * 8 + sub * 4 + hf * 2 + 1] + bv.y;
                    *(float2*)(op + co) = v;
                }
            }
        }
        __syncthreads();   // before overwriting W tile
    }
}

// ---------------- fused edge kernel (2-D tiling + staged coalesced epilogue) -
// Ce = e @ W_C^T; e_new = Ce + bC + Dh[src] + Eh[dst]; store e_new; col stats.
__global__ __launch_bounds__(256, 2) void k_edge_tc(
    const float* __restrict__ Ein,
    const float* __restrict__ bias,
    const int* __restrict__ src, const int* __restrict__ dst)
{
    extern __shared__ __align__(16) char sb[];
    float* shs = (float*)(sb + O_ST);
    float* shq = shs + DD;
    const int tid = threadIdx.x, wid = tid >> 5, lane = tid & 31;
    const int wm = wid >> 1, wn = wid & 1;
    const int row0 = blockIdx.x * TM;
    const int q = lane >> 2, cpair = (lane & 3) * 2;

    if (tid < DD) { shs[tid] = 0.f; shq[tid] = 0.f; }

    copy_w(g_Wh + 4 * DD * DD, sb + O_BH, tid);
    __syncthreads();

    float acc[64];
#pragma unroll
    for (int i = 0; i < 64; i++) acc[i] = 0.f;
    mma_regA2(Ein, row0, NE, smem_u32(sb) + O_BH, wm, wn, lane, acc);

    // prefetch gather indices for the (ty,tx) epilogue mapping
    const int ty = tid >> 4, tx = tid & 15;
    int sArr[8], dArr[8];
#pragma unroll
    for (int r = 0; r < 8; r++) {
        int m = row0 + ty * 8 + r;
        sArr[r] = (m < NE) ? src[m] : 0;
        dArr[r] = (m < NE) ? dst[m] : 0;
    }

    __syncthreads();   // all warps done reading B smem before overlay

    // stage C into smem (float, stride 132) over the B region
    float* Csm = (float*)(sb + O_BH);
#pragma unroll
    for (int mt = 0; mt < 2; mt++)
#pragma unroll
    for (int hf = 0; hf < 2; hf++) {
        int rr = wm * 32 + mt * 16 + hf * 8 + q;
#pragma unroll
        for (int p = 0; p < 4; p++)
#pragma unroll
        for (int sub = 0; sub < 2; sub++) {
            int co = wn * 64 + p * 16 + sub * 8 + cpair;
            float2 v;
            v.x = acc[(mt * 4 + p) * 8 + sub * 4 + hf * 2 + 0];
            v.y = acc[(mt * 4 + p) * 8 + sub * 4 + hf * 2 + 1];
            *(float2*)(Csm + rr * CSTRIDE + co) = v;
        }
    }
    __syncthreads();

    // coalesced epilogue: thread (ty,tx) -> 8 rows x 8 contiguous cols
    const int n0 = tx * 8;
    float bv[8];
#pragma unroll
    for (int c = 0; c < 8; c++) bv[c] = bias[n0 + c];
    float cs[8], cq[8];
#pragma unroll
    for (int c = 0; c < 8; c++) { cs[c] = 0.f; cq[c] = 0.f; }

#pragma unroll
    for (int r = 0; r < 8; r++) {
        int tr = ty * 8 + r;
        int m = row0 + tr;
        if (m < NE) {
            const float* Dr = g_Dh + (size_t)sArr[r] * DD + n0;
            const float* Er = g_Eh + (size_t)dArr[r] * DD + n0;
            float4 D0 = *(const float4*)Dr, D1 = *(const float4*)(Dr + 4);
            float4 E0 = *(const float4*)Er, E1 = *(const float4*)(Er + 4);
            float Dv[8] = {D0.x, D0.y, D0.z, D0.w, D1.x, D1.y, D1.z, D1.w};
            float Ev[8] = {E0.x, E0.y, E0.z, E0.w, E1.x, E1.y, E1.z, E1.w};
            float en[8];
#pragma unroll
            for (int c = 0; c < 8; c++) {
                en[c] = Csm[tr * CSTRIDE + n0 + c] + bv[c] + Dv[c] + Ev[c];
                cs[c] += en[c];
                cq[c] += en[c] * en[c];
            }
            float* ep = g_enew + (size_t)m * DD + n0;
            float4 o0 = {en[0], en[1], en[2], en[3]};
            float4 o1 = {en[4], en[5], en[6], en[7]};
            *(float4*)ep = o0; *(float4*)(ep + 4) = o1;
        }
    }
#pragma unroll
    for (int c = 0; c < 8; c++) {
        atomicAdd(&shs[n0 + c], cs[c]);
        atomicAdd(&shq[n0 + c], cq[c]);
    }
    __syncthreads();
    if (tid < DD) {
        atomicAdd(&g_stats[tid], shs[tid]);
        atomicAdd(&g_stats[DD + tid], shq[tid]);
    }
}

// ---------------- gather-side aggregation + h_new + h stats ------------------
__global__ __launch_bounds__(128) void k_agg(const int* __restrict__ src) {
    const int col = threadIdx.x;   // 0..127
    float ls = 0.f, lq = 0.f;
    for (int n = blockIdx.x; n < NN; n += gridDim.x) {
        int s0 = g_off[n], s1 = g_off[n + 1];
        float num = 0.f, den = 0.f;
        int eid_n = 0, sv_n = 0;
        if (s0 < s1) { eid_n = g_eid[s0]; sv_n = src[eid_n]; }
        for (int i = s0; i < s1; i++) {
            int eid = eid_n, sv = sv_n;
            if (i + 1 < s1) { eid_n = g_eid[i + 1]; sv_n = src[eid_n]; }
            float en = g_enew[(size_t)eid * DD + col];
            float bh = g_Bh[(size_t)sv * DD + col];
            float sg = 1.f / (1.f + __expf(-en));
            den += sg;
            num += bh * sg;
        }
        float v = g_Ah[(size_t)n * DD + col] + num / (den + 1e-6f);
        g_hnew[(size_t)n * DD + col] = v;
        ls += v; lq += v * v;
    }
    atomicAdd(&g_stats[2 * DD + col], ls);
    atomicAdd(&g_stats[3 * DD + col], lq);
}

// ---------------- BN(train) + relu + residual epilogue ----------------------
__global__ void k_out(const float* __restrict__ x, const float* __restrict__ v,
                      const float* __restrict__ gamma, const float* __restrict__ beta,
                      float* __restrict__ out, size_t n4, int statbase, float invM)
{
    __shared__ float sc[DD];
    __shared__ float sf[DD];
    const int tid = threadIdx.x;
    if (tid < DD) {
        float mean = g_stats[statbase * DD + tid] * invM;
        float var = g_stats[(statbase + 1) * DD + tid] * invM - mean * mean;
        float s = rsqrtf(var + 1e-5f) * gamma[tid];
        sc[tid] = s;
        sf[tid] = beta[tid] - mean * s;
    }
    __syncthreads();
    size_t i = (size_t)blockIdx.x * 256 + tid;
    if (i < n4) {
        int c0 = (int)((i * 4) & (DD - 1));
        float4 vv = ((const float4*)v)[i];
        float4 xx = ((const float4*)x)[i];
        float4 o;
        o.x = xx.x + fmaxf(fmaf(vv.x, sc[c0 + 0], sf[c0 + 0]), 0.f);
        o.y = xx.y + fmaxf(fmaf(vv.y, sc[c0 + 1], sf[c0 + 1]), 0.f);
        o.z = xx.z + fmaxf(fmaf(vv.z, sc[c0 + 2], sf[c0 + 2]), 0.f);
        o.w = xx.w + fmaxf(fmaf(vv.w, sc[c0 + 3], sf[c0 + 3]), 0.f);
        ((float4*)out)[i] = o;
    }
}

// ---------------- host orchestration ----------------------------------------
extern "C" void kernel_launch(void* const* d_in, const int* in_sizes, int n_in,
                              void* d_out, int out_size)
{
    const float* h   = (const float*)d_in[0];
    const float* e   = (const float*)d_in[1];
    const int* src   = (const int*)d_in[2];
    const int* dst   = (const int*)d_in[3];
    const float* W_A = (const float*)d_in[4];
    const float* b_A = (const float*)d_in[5];
    const float* W_B = (const float*)d_in[6];
    const float* b_B = (const float*)d_in[7];
    const float* W_C = (const float*)d_in[8];
    const float* b_C = (const float*)d_in[9];
    const float* W_D = (const float*)d_in[10];
    const float* b_D = (const float*)d_in[11];
    const float* W_E = (const float*)d_in[12];
    const float* b_E = (const float*)d_in[13];
    const float* gamma_h = (const float*)d_in[14];
    const float* beta_h  = (const float*)d_in[15];
    const float* gamma_e = (const float*)d_in[16];
    const float* beta_e  = (const float*)d_in[17];
    float* out = (float*)d_out;

    float *pAh, *pBh, *pDh, *pEh, *pHnew, *pEnew;
    cudaGetSymbolAddress((void**)&pAh, g_Ah);
    cudaGetSymbolAddress((void**)&pBh, g_Bh);
    cudaGetSymbolAddress((void**)&pDh, g_Dh);
    cudaGetSymbolAddress((void**)&pEh, g_Eh);
    cudaGetSymbolAddress((void**)&pHnew, g_hnew);
    cudaGetSymbolAddress((void**)&pEnew, g_enew);

    cudaFuncSetAttribute(k_gemm4, cudaFuncAttributeMaxDynamicSharedMemorySize, DSMEM_BYTES);
    cudaFuncSetAttribute(k_edge_tc, cudaFuncAttributeMaxDynamicSharedMemorySize, DSMEM_BYTES);

    const int gemmN = (NN + TM - 1) / TM;   // 391
    const int gemmE = (NE + TM - 1) / TM;   // 3907

    // submission order puts k_edge_tc 4th (ncu capture lands on launch #4)
    k_zero<<<(NN + 255) / 256, 256>>>();
    {
        dim3 g(DD * DD / 256, 5);
        k_convW<<<g, 256>>>(W_A, W_B, W_D, W_E, W_C);
    }
    k_gemm4<<<gemmN, 256, DSMEM_BYTES>>>(h, b_A, b_B, b_D, b_E, pAh, pBh, pDh, pEh);
    k_edge_tc<<<gemmE, 256, DSMEM_BYTES>>>(e, b_C, src, dst);
    k_hist<<<(NE + 255) / 256, 256>>>(dst);
    k_scan1<<<SCAN_B, 1024>>>();
    k_scan2<<<1, 32>>>();
    k_scan3<<<SCAN_B, 1024>>>();
    k_scatter<<<(NE + 255) / 256, 256>>>(dst);
    k_agg<<<4096, 128>>>(src);
    // e_out: rows after h_out section
    k_out<<<(int)(((size_t)NE * DD / 4 + 255) / 256), 256>>>(
        e, pEnew, gamma_e, beta_e, out + (size_t)NN * DD, (size_t)NE * DD / 4, 0, 1.f / NE);
    // h_out at the front of d_out
    k_out<<<(int)(((size_t)NN * DD / 4 + 255) / 256), 256>>>(
        h, pHnew, gamma_h, beta_h, out, (size_t)NN * DD / 4, 2, 1.f / NN);
}